// round 1
// baseline (speedup 1.0000x reference)
#include <cuda_runtime.h>

#define SEQ  2048
#define HID  2048
#define NH   16
#define HD   128
#define BATCH 2
#define ATTN_SCALE 0.08838834764831845f

// Scratch (no allocs allowed): qkv [2,2048,6144], attn out [2,2048,2048]
__device__ float g_qkv[BATCH * SEQ * 3 * HID];
__device__ float g_attn[BATCH * SEQ * HID];

// ---------------------------------------------------------------------------
// C[M,N] = A[M,K] * B[N,K]^T   (both A and B row-major, K contiguous)
// 128x128 tile, BK=8, 256 threads, 8x8 per thread.
// M,N % 128 == 0, K % 8 == 0 (true for all calls here).
// ---------------------------------------------------------------------------
__global__ __launch_bounds__(256) void sgemm_abt(
    int M, int N, int K,
    const float* __restrict__ A,
    const float* __restrict__ B,
    float* __restrict__ C)
{
    __shared__ float As[8][128];
    __shared__ float Bs[8][128];

    const int tid = threadIdx.x;
    const int threadRow = tid / 16;       // 0..15
    const int threadCol = tid % 16;       // 0..15

    A += (size_t)blockIdx.y * 128 * K;
    B += (size_t)blockIdx.x * 128 * K;
    C += (size_t)blockIdx.y * 128 * N + blockIdx.x * 128;

    const int loadRow = tid / 2;          // 0..127
    const int loadCol = (tid % 2) * 4;    // 0 or 4

    float acc[8][8];
#pragma unroll
    for (int i = 0; i < 8; i++)
#pragma unroll
        for (int j = 0; j < 8; j++) acc[i][j] = 0.0f;

    for (int k0 = 0; k0 < K; k0 += 8) {
        float4 a = *(const float4*)&A[(size_t)loadRow * K + k0 + loadCol];
        float4 b = *(const float4*)&B[(size_t)loadRow * K + k0 + loadCol];
        As[loadCol + 0][loadRow] = a.x;
        As[loadCol + 1][loadRow] = a.y;
        As[loadCol + 2][loadRow] = a.z;
        As[loadCol + 3][loadRow] = a.w;
        Bs[loadCol + 0][loadRow] = b.x;
        Bs[loadCol + 1][loadRow] = b.y;
        Bs[loadCol + 2][loadRow] = b.z;
        Bs[loadCol + 3][loadRow] = b.w;
        __syncthreads();

#pragma unroll
        for (int kk = 0; kk < 8; kk++) {
            float4 a0 = *(const float4*)&As[kk][threadRow * 8];
            float4 a1 = *(const float4*)&As[kk][threadRow * 8 + 4];
            float4 b0 = *(const float4*)&Bs[kk][threadCol * 8];
            float4 b1 = *(const float4*)&Bs[kk][threadCol * 8 + 4];
            float ra[8] = {a0.x, a0.y, a0.z, a0.w, a1.x, a1.y, a1.z, a1.w};
            float rb[8] = {b0.x, b0.y, b0.z, b0.w, b1.x, b1.y, b1.z, b1.w};
#pragma unroll
            for (int i = 0; i < 8; i++)
#pragma unroll
                for (int j = 0; j < 8; j++)
                    acc[i][j] += ra[i] * rb[j];
        }
        __syncthreads();
    }

#pragma unroll
    for (int i = 0; i < 8; i++) {
        int row = threadRow * 8 + i;
        float4 c0 = make_float4(acc[i][0], acc[i][1], acc[i][2], acc[i][3]);
        float4 c1 = make_float4(acc[i][4], acc[i][5], acc[i][6], acc[i][7]);
        *(float4*)&C[(size_t)row * N + threadCol * 8]     = c0;
        *(float4*)&C[(size_t)row * N + threadCol * 8 + 4] = c1;
    }
}

// ---------------------------------------------------------------------------
// Flash-style attention tile: Br=64 queries per block, Bc=32 keys per chunk.
// qkv layout: [b, s, 6144] with Q at col 0, K at 2048, V at 4096; head h
// occupies cols h*128..h*128+127 of its segment.
// Output: attn_out [b, s, 2048] with head h at cols h*128..+127 (concat).
// 256 threads = 16x16; each thread: 4 S-rows x 2 S-cols, O tile 4x8.
// ---------------------------------------------------------------------------
#define BR 64
#define BC 32

__global__ __launch_bounds__(256) void attn_kernel(
    const float* __restrict__ qkv,
    float* __restrict__ attn_out)
{
    const int q0 = blockIdx.x * BR;
    const int h  = blockIdx.y;
    const int b  = blockIdx.z;
    const int tid = threadIdx.x;
    const int tx = tid % 16;   // S cols / O cols
    const int ty = tid / 16;   // S rows / O rows

    __shared__ float Qs[BR][HD + 4];     // 64 x 132
    __shared__ float Ks[BC][HD + 4];     // 32 x 132
    __shared__ float Vs[BC][HD + 4];     // 32 x 132
    __shared__ float Ps[BR][BC + 4];     // 64 x 36

    const int q_off = 0;
    const int k_off = HID;
    const int v_off = 2 * HID;

    // Load Q tile (64 x 128)
    for (int i = tid; i < BR * 32; i += 256) {
        int row = i / 32;
        int c4  = (i % 32) * 4;
        float4 v = *(const float4*)&qkv[((size_t)(b * SEQ + q0 + row)) * (3 * HID) + q_off + h * HD + c4];
        *(float4*)&Qs[row][c4] = v;
    }

    float m_run[4], l_run[4];
    float o[4][8];
#pragma unroll
    for (int i = 0; i < 4; i++) {
        m_run[i] = -1e30f;
        l_run[i] = 0.0f;
#pragma unroll
        for (int c = 0; c < 8; c++) o[i][c] = 0.0f;
    }

    const int ty4 = ty * 4;
    const int tx2 = tx * 2;
    const int tx8 = tx * 8;

    for (int nc = 0; nc < SEQ / BC; nc++) {
        const int j0 = nc * BC;
        __syncthreads();   // previous chunk fully consumed

        // Load K, V chunks (32 x 128 each)
        for (int i = tid; i < BC * 32; i += 256) {
            int row = i / 32;
            int c4  = (i % 32) * 4;
            size_t base = ((size_t)(b * SEQ + j0 + row)) * (3 * HID) + h * HD + c4;
            *(float4*)&Ks[row][c4] = *(const float4*)&qkv[base + k_off];
            *(float4*)&Vs[row][c4] = *(const float4*)&qkv[base + v_off];
        }
        __syncthreads();

        // S = Q * K^T (scaled): each thread 4 rows x 2 cols
        float acc[4][2];
#pragma unroll
        for (int i = 0; i < 4; i++) { acc[i][0] = 0.0f; acc[i][1] = 0.0f; }

#pragma unroll 8
        for (int kk = 0; kk < HD; kk += 4) {
            float4 k0 = *(const float4*)&Ks[tx2 + 0][kk];
            float4 k1 = *(const float4*)&Ks[tx2 + 1][kk];
#pragma unroll
            for (int i = 0; i < 4; i++) {
                float4 qv = *(const float4*)&Qs[ty4 + i][kk];
                acc[i][0] += qv.x * k0.x + qv.y * k0.y + qv.z * k0.z + qv.w * k0.w;
                acc[i][1] += qv.x * k1.x + qv.y * k1.y + qv.z * k1.z + qv.w * k1.w;
            }
        }

        // Online softmax: row reductions over 16-lane groups (same ty)
#pragma unroll
        for (int i = 0; i < 4; i++) {
            acc[i][0] *= ATTN_SCALE;
            acc[i][1] *= ATTN_SCALE;
            float mloc = fmaxf(acc[i][0], acc[i][1]);
#pragma unroll
            for (int off = 8; off >= 1; off >>= 1)
                mloc = fmaxf(mloc, __shfl_xor_sync(0xffffffffu, mloc, off));
            float m_new = fmaxf(m_run[i], mloc);
            float corr  = __expf(m_run[i] - m_new);
            float p0 = __expf(acc[i][0] - m_new);
            float p1 = __expf(acc[i][1] - m_new);
            float lloc = p0 + p1;
#pragma unroll
            for (int off = 8; off >= 1; off >>= 1)
                lloc += __shfl_xor_sync(0xffffffffu, lloc, off);
            l_run[i] = l_run[i] * corr + lloc;
            m_run[i] = m_new;
#pragma unroll
            for (int c = 0; c < 8; c++) o[i][c] *= corr;
            Ps[ty4 + i][tx2 + 0] = p0;
            Ps[ty4 + i][tx2 + 1] = p1;
        }
        __syncthreads();

        // O += P * V : each thread 4 rows x 8 cols
#pragma unroll 8
        for (int j = 0; j < BC; j++) {
            float4 v0 = *(const float4*)&Vs[j][tx8];
            float4 v1 = *(const float4*)&Vs[j][tx8 + 4];
#pragma unroll
            for (int i = 0; i < 4; i++) {
                float p = Ps[ty4 + i][j];
                o[i][0] += p * v0.x; o[i][1] += p * v0.y;
                o[i][2] += p * v0.z; o[i][3] += p * v0.w;
                o[i][4] += p * v1.x; o[i][5] += p * v1.y;
                o[i][6] += p * v1.z; o[i][7] += p * v1.w;
            }
        }
    }

    // Normalize and write out: [b, q, h*128 + c]
#pragma unroll
    for (int i = 0; i < 4; i++) {
        float inv = 1.0f / l_run[i];
        int row = q0 + ty4 + i;
        size_t base = ((size_t)(b * SEQ + row)) * HID + h * HD + tx8;
        float4 o0 = make_float4(o[i][0] * inv, o[i][1] * inv, o[i][2] * inv, o[i][3] * inv);
        float4 o1 = make_float4(o[i][4] * inv, o[i][5] * inv, o[i][6] * inv, o[i][7] * inv);
        *(float4*)&attn_out[base]     = o0;
        *(float4*)&attn_out[base + 4] = o1;
    }
}

// ---------------------------------------------------------------------------
extern "C" void kernel_launch(void* const* d_in, const int* in_sizes, int n_in,
                              void* d_out, int out_size)
{
    const float* x      = (const float*)d_in[0];   // [2,2048,2048]
    const float* w_qkv  = (const float*)d_in[1];   // [6144,2048]
    const float* w_proj = (const float*)d_in[2];   // [2048,2048]
    float* out = (float*)d_out;                    // [2,2048,2048]

    float* qkv_ptr  = nullptr;
    float* attn_ptr = nullptr;
    cudaGetSymbolAddress((void**)&qkv_ptr,  g_qkv);
    cudaGetSymbolAddress((void**)&attn_ptr, g_attn);

    const int M = BATCH * SEQ;  // 4096

    // 1) qkv = x @ w_qkv^T : [4096, 6144]
    sgemm_abt<<<dim3((3 * HID) / 128, M / 128), 256>>>(M, 3 * HID, HID, x, w_qkv, qkv_ptr);

    // 2) attention: [2,2048,2048] (heads concatenated)
    attn_kernel<<<dim3(SEQ / BR, NH, BATCH), 256>>>(qkv_ptr, attn_ptr);

    // 3) out = attn @ w_proj^T : [4096, 2048]
    sgemm_abt<<<dim3(HID / 128, M / 128), 256>>>(M, HID, HID, attn_ptr, w_proj, out);
}

// round 3
// speedup vs baseline: 1.6570x; 1.6570x over previous
#include <cuda_runtime.h>
#include <cuda_bf16.h>
#include <cstdint>

#define SEQ  2048
#define HID  2048
#define NH   16
#define HD   128
#define BATCH 2
#define ATTN_SCALE 0.08838834764831845f
#define KP   6144   // split K' = 3*2048

// ---------------- scratch (no allocs allowed) ----------------
__device__ float g_qkv[BATCH * SEQ * 3 * HID];
__device__ float g_attn[BATCH * SEQ * HID];
__device__ __nv_bfloat16 g_as[BATCH * SEQ * KP];   // split A operand
__device__ __nv_bfloat16 g_ws1[3 * HID * KP];      // split w_qkv
__device__ __nv_bfloat16 g_ws2[HID * KP];          // split w_proj

__device__ __forceinline__ uint32_t smem_to_u32(const void* p) {
    uint32_t a;
    asm("{ .reg .u64 t; cvta.to.shared.u64 t, %1; cvt.u32.u64 %0, t; }" : "=r"(a) : "l"(p));
    return a;
}

// ---------------------------------------------------------------------------
// split: fp32 [R,K] -> bf16 [R,3K].  mode 0 (A operand): [hi | lo | hi]
//                                    mode 1 (B operand): [hi | hi | lo]
// ---------------------------------------------------------------------------
__global__ __launch_bounds__(256) void split_kernel(
    const float* __restrict__ in, __nv_bfloat16* __restrict__ out,
    int R, int K, int mode)
{
    int total = R * K;
    for (int i = blockIdx.x * blockDim.x + threadIdx.x; i < total;
         i += gridDim.x * blockDim.x) {
        int r = i / K, c = i % K;
        float a = in[i];
        __nv_bfloat16 hi = __float2bfloat16(a);
        __nv_bfloat16 lo = __float2bfloat16(a - __bfloat162float(hi));
        size_t base = (size_t)r * (3 * K) + c;
        out[base]         = hi;
        out[base + K]     = mode ? hi : lo;
        out[base + 2 * K] = mode ? lo : hi;
    }
}

// ---------------------------------------------------------------------------
// bf16 mma.sync GEMM: C[M,N] = A[M,KP] * B[N,KP]^T  (both bf16, K contiguous)
// CTA tile 128x128, BK=64, 3-stage cp.async pipeline, 8 warps (64x32 each).
// SMEM: rows of 128B (64 bf16), 16B-chunk swizzle  c ^= (row & 7)  -> LDSM
// conflict-free.
// ---------------------------------------------------------------------------
#define BM 128
#define BN 128
#define BK 64
#define STAGES 3
#define STAGE_BYTES (BM * 128 + BN * 128)      // 32768
#define SM_TOTAL_G (STAGES * STAGE_BYTES)      // 98304

__device__ __forceinline__ void cp_async16(uint32_t dst, const void* src) {
    asm volatile("cp.async.cg.shared.global [%0], [%1], 16;" :: "r"(dst), "l"(src));
}
__device__ __forceinline__ void cp_commit() {
    asm volatile("cp.async.commit_group;" ::: "memory");
}
__device__ __forceinline__ void cp_wait1() {
    asm volatile("cp.async.wait_group 1;" ::: "memory");
}

__device__ __forceinline__ void ldsm_x4(uint32_t& r0, uint32_t& r1,
                                        uint32_t& r2, uint32_t& r3, uint32_t addr) {
    asm volatile("ldmatrix.sync.aligned.m8n8.x4.shared.b16 {%0,%1,%2,%3}, [%4];"
        : "=r"(r0), "=r"(r1), "=r"(r2), "=r"(r3) : "r"(addr));
}

__device__ __forceinline__ void mma_bf16(float& c0, float& c1, float& c2, float& c3,
                                         uint32_t a0, uint32_t a1, uint32_t a2, uint32_t a3,
                                         uint32_t b0, uint32_t b1) {
    asm volatile(
        "mma.sync.aligned.m16n8k16.row.col.f32.bf16.bf16.f32 "
        "{%0,%1,%2,%3}, {%4,%5,%6,%7}, {%8,%9}, {%0,%1,%2,%3};"
        : "+f"(c0), "+f"(c1), "+f"(c2), "+f"(c3)
        : "r"(a0), "r"(a1), "r"(a2), "r"(a3), "r"(b0), "r"(b1));
}

__global__ void __launch_bounds__(256, 2) gemm_mma(
    int M, int N,
    const __nv_bfloat16* __restrict__ A,
    const __nv_bfloat16* __restrict__ B,
    float* __restrict__ C)
{
    extern __shared__ char smem[];
    const uint32_t smem_u = smem_to_u32(smem);
    const int tid  = threadIdx.x;
    const int wid  = tid >> 5;
    const int lane = tid & 31;
    const int wm = wid & 1;          // 2 warps along M (64 rows each)
    const int wn = wid >> 1;         // 4 warps along N (32 cols each)
    const int m0 = blockIdx.y * BM;
    const int n0 = blockIdx.x * BN;

    const int NT = KP / BK;          // 96

    // cp.async load helper indices: 2048 chunks per stage (A:1024, B:1024);
    // each thread loads 8 chunks (4 for A, 4 for B).
    auto load_stage = [&](int kt, int stage) {
        const uint32_t sA = smem_u + stage * STAGE_BYTES;
        const uint32_t sB = sA + BM * 128;
        const int k0 = kt * BK;
#pragma unroll
        for (int j = 0; j < 4; j++) {
            int i = tid + j * 256;        // 0..1023
            int row = i >> 3;             // 0..127
            int c   = i & 7;              // chunk 0..7
            uint32_t dsw = (uint32_t)(row * 128 + ((c ^ (row & 7)) << 4));
            cp_async16(sA + dsw, A + (size_t)(m0 + row) * KP + k0 + c * 8);
            cp_async16(sB + dsw, B + (size_t)(n0 + row) * KP + k0 + c * 8);
        }
        cp_commit();
    };

    float acc[4][4][4];
#pragma unroll
    for (int i = 0; i < 4; i++)
#pragma unroll
        for (int j = 0; j < 4; j++)
#pragma unroll
            for (int k = 0; k < 4; k++) acc[i][j][k] = 0.0f;

    // prologue: stages 0,1
    load_stage(0, 0);
    load_stage(1, 1);

    // precomputed ldmatrix lane addressing
    const int a_row = wm * 64 + (lane & 15);          // + mi*16
    const int a_chk = lane >> 4;                      // + ks*2
    const int b_row = wn * 32 + (lane & 7) + (((lane >> 4) & 1) << 3);  // + p*16
    const int b_chk = (lane >> 3) & 1;                // + ks*2

    for (int kt = 0; kt < NT; kt++) {
        const int stage = kt % STAGES;
        cp_wait1();
        __syncthreads();

        if (kt + 2 < NT) load_stage(kt + 2, (kt + 2) % STAGES);

        const uint32_t sA = smem_u + stage * STAGE_BYTES;
        const uint32_t sB = sA + BM * 128;

#pragma unroll
        for (int ks = 0; ks < 4; ks++) {
            uint32_t a[4][4];
#pragma unroll
            for (int mi = 0; mi < 4; mi++) {
                int row = a_row + mi * 16;
                int chk = ks * 2 + a_chk;
                uint32_t addr = sA + (uint32_t)(row * 128 + ((chk ^ (row & 7)) << 4));
                ldsm_x4(a[mi][0], a[mi][1], a[mi][2], a[mi][3], addr);
            }
            uint32_t b[4][2];
#pragma unroll
            for (int p = 0; p < 2; p++) {
                int row = b_row + p * 16;
                int chk = ks * 2 + b_chk;
                uint32_t addr = sB + (uint32_t)(row * 128 + ((chk ^ (row & 7)) << 4));
                ldsm_x4(b[p * 2][0], b[p * 2][1], b[p * 2 + 1][0], b[p * 2 + 1][1], addr);
            }
#pragma unroll
            for (int mi = 0; mi < 4; mi++)
#pragma unroll
                for (int ni = 0; ni < 4; ni++)
                    mma_bf16(acc[mi][ni][0], acc[mi][ni][1], acc[mi][ni][2], acc[mi][ni][3],
                             a[mi][0], a[mi][1], a[mi][2], a[mi][3],
                             b[ni][0], b[ni][1]);
        }
        __syncthreads();
    }

    // epilogue: direct global writes (c frag: rows l/4 & l/4+8, cols 2*(l%4))
    const int cr = lane >> 2;
    const int cc = (lane & 3) * 2;
#pragma unroll
    for (int mi = 0; mi < 4; mi++) {
        int row = m0 + wm * 64 + mi * 16 + cr;
#pragma unroll
        for (int ni = 0; ni < 4; ni++) {
            int col = n0 + wn * 32 + ni * 8 + cc;
            float2 v0 = make_float2(acc[mi][ni][0], acc[mi][ni][1]);
            float2 v1 = make_float2(acc[mi][ni][2], acc[mi][ni][3]);
            *reinterpret_cast<float2*>(C + (size_t)row * N + col) = v0;
            *reinterpret_cast<float2*>(C + (size_t)(row + 8) * N + col) = v1;
        }
    }
}

// ---------------------------------------------------------------------------
// Flash-style fp32 attention (known correct, round-1)
// ---------------------------------------------------------------------------
#define BR 64
#define BC 32

__global__ __launch_bounds__(256) void attn_kernel(
    const float* __restrict__ qkv,
    float* __restrict__ attn_out)
{
    const int q0 = blockIdx.x * BR;
    const int h  = blockIdx.y;
    const int b  = blockIdx.z;
    const int tid = threadIdx.x;
    const int tx = tid % 16;
    const int ty = tid / 16;

    __shared__ float Qs[BR][HD + 4];
    __shared__ float Ks[BC][HD + 4];
    __shared__ float Vs[BC][HD + 4];
    __shared__ float Ps[BR][BC + 4];

    const int k_off = HID;
    const int v_off = 2 * HID;

    for (int i = tid; i < BR * 32; i += 256) {
        int row = i / 32;
        int c4  = (i % 32) * 4;
        float4 v = *(const float4*)&qkv[((size_t)(b * SEQ + q0 + row)) * (3 * HID) + h * HD + c4];
        *(float4*)&Qs[row][c4] = v;
    }

    float m_run[4], l_run[4];
    float o[4][8];
#pragma unroll
    for (int i = 0; i < 4; i++) {
        m_run[i] = -1e30f;
        l_run[i] = 0.0f;
#pragma unroll
        for (int c = 0; c < 8; c++) o[i][c] = 0.0f;
    }

    const int ty4 = ty * 4;
    const int tx2 = tx * 2;
    const int tx8 = tx * 8;

    for (int nc = 0; nc < SEQ / BC; nc++) {
        const int j0 = nc * BC;
        __syncthreads();

        for (int i = tid; i < BC * 32; i += 256) {
            int row = i / 32;
            int c4  = (i % 32) * 4;
            size_t base = ((size_t)(b * SEQ + j0 + row)) * (3 * HID) + h * HD + c4;
            *(float4*)&Ks[row][c4] = *(const float4*)&qkv[base + k_off];
            *(float4*)&Vs[row][c4] = *(const float4*)&qkv[base + v_off];
        }
        __syncthreads();

        float acc[4][2];
#pragma unroll
        for (int i = 0; i < 4; i++) { acc[i][0] = 0.0f; acc[i][1] = 0.0f; }

#pragma unroll 8
        for (int kk = 0; kk < HD; kk += 4) {
            float4 kv0 = *(const float4*)&Ks[tx2 + 0][kk];
            float4 kv1 = *(const float4*)&Ks[tx2 + 1][kk];
#pragma unroll
            for (int i = 0; i < 4; i++) {
                float4 qv = *(const float4*)&Qs[ty4 + i][kk];
                acc[i][0] += qv.x * kv0.x + qv.y * kv0.y + qv.z * kv0.z + qv.w * kv0.w;
                acc[i][1] += qv.x * kv1.x + qv.y * kv1.y + qv.z * kv1.z + qv.w * kv1.w;
            }
        }

#pragma unroll
        for (int i = 0; i < 4; i++) {
            acc[i][0] *= ATTN_SCALE;
            acc[i][1] *= ATTN_SCALE;
            float mloc = fmaxf(acc[i][0], acc[i][1]);
#pragma unroll
            for (int off = 8; off >= 1; off >>= 1)
                mloc = fmaxf(mloc, __shfl_xor_sync(0xffffffffu, mloc, off));
            float m_new = fmaxf(m_run[i], mloc);
            float corr  = __expf(m_run[i] - m_new);
            float p0 = __expf(acc[i][0] - m_new);
            float p1 = __expf(acc[i][1] - m_new);
            float lloc = p0 + p1;
#pragma unroll
            for (int off = 8; off >= 1; off >>= 1)
                lloc += __shfl_xor_sync(0xffffffffu, lloc, off);
            l_run[i] = l_run[i] * corr + lloc;
            m_run[i] = m_new;
#pragma unroll
            for (int c = 0; c < 8; c++) o[i][c] *= corr;
            Ps[ty4 + i][tx2 + 0] = p0;
            Ps[ty4 + i][tx2 + 1] = p1;
        }
        __syncthreads();

#pragma unroll 8
        for (int j = 0; j < BC; j++) {
            float4 v0 = *(const float4*)&Vs[j][tx8];
            float4 v1 = *(const float4*)&Vs[j][tx8 + 4];
#pragma unroll
            for (int i = 0; i < 4; i++) {
                float p = Ps[ty4 + i][j];
                o[i][0] += p * v0.x; o[i][1] += p * v0.y;
                o[i][2] += p * v0.z; o[i][3] += p * v0.w;
                o[i][4] += p * v1.x; o[i][5] += p * v1.y;
                o[i][6] += p * v1.z; o[i][7] += p * v1.w;
            }
        }
    }

#pragma unroll
    for (int i = 0; i < 4; i++) {
        float inv = 1.0f / l_run[i];
        int row = q0 + ty4 + i;
        size_t base = ((size_t)(b * SEQ + row)) * HID + h * HD + tx8;
        float4 o0 = make_float4(o[i][0] * inv, o[i][1] * inv, o[i][2] * inv, o[i][3] * inv);
        float4 o1 = make_float4(o[i][4] * inv, o[i][5] * inv, o[i][6] * inv, o[i][7] * inv);
        *(float4*)&attn_out[base]     = o0;
        *(float4*)&attn_out[base + 4] = o1;
    }
}

// ---------------------------------------------------------------------------
extern "C" void kernel_launch(void* const* d_in, const int* in_sizes, int n_in,
                              void* d_out, int out_size)
{
    const float* x      = (const float*)d_in[0];
    const float* w_qkv  = (const float*)d_in[1];
    const float* w_proj = (const float*)d_in[2];
    float* out = (float*)d_out;

    float* qkv_ptr  = nullptr;
    float* attn_ptr = nullptr;
    __nv_bfloat16 *as_ptr = nullptr, *ws1_ptr = nullptr, *ws2_ptr = nullptr;
    cudaGetSymbolAddress((void**)&qkv_ptr,  g_qkv);
    cudaGetSymbolAddress((void**)&attn_ptr, g_attn);
    cudaGetSymbolAddress((void**)&as_ptr,  g_as);
    cudaGetSymbolAddress((void**)&ws1_ptr, g_ws1);
    cudaGetSymbolAddress((void**)&ws2_ptr, g_ws2);

    cudaFuncSetAttribute(gemm_mma,
                         cudaFuncAttributeMaxDynamicSharedMemorySize, SM_TOTAL_G);

    const int M = BATCH * SEQ;  // 4096

    // splits (bf16x3 via K-concat)
    split_kernel<<<4096, 256>>>(x,      as_ptr,  M,       HID, 0);
    split_kernel<<<4096, 256>>>(w_qkv,  ws1_ptr, 3 * HID, HID, 1);
    split_kernel<<<2048, 256>>>(w_proj, ws2_ptr, HID,     HID, 1);

    // 1) qkv = x @ w_qkv^T : [4096, 6144]
    gemm_mma<<<dim3(3 * HID / BN, M / BM), 256, SM_TOTAL_G>>>(
        M, 3 * HID, as_ptr, ws1_ptr, qkv_ptr);

    // 2) attention
    attn_kernel<<<dim3(SEQ / BR, NH, BATCH), 256>>>(qkv_ptr, attn_ptr);

    // 3) out = attn @ w_proj^T : [4096, 2048]
    split_kernel<<<4096, 256>>>(attn_ptr, as_ptr, M, HID, 0);
    gemm_mma<<<dim3(HID / BN, M / BM), 256, SM_TOTAL_G>>>(
        M, HID, as_ptr, ws2_ptr, out);
}

// round 4
// speedup vs baseline: 3.9056x; 2.3571x over previous
#include <cuda_runtime.h>
#include <cuda_bf16.h>
#include <cstdint>

#define SEQ  2048
#define HID  2048
#define NH   16
#define HD   128
#define BATCH 2
#define ATTN_SCALE 0.08838834764831845f
#define KP   6144   // split K' = 3*2048

// ---------------- scratch (no allocs allowed) ----------------
__device__ float g_qkv[BATCH * SEQ * 3 * HID];
__device__ __nv_bfloat16 g_as[BATCH * SEQ * KP];   // split A operand (x, later attn out)
__device__ __nv_bfloat16 g_ws1[3 * HID * KP];      // split w_qkv
__device__ __nv_bfloat16 g_ws2[HID * KP];          // split w_proj
// attention operands, [b*NH+h][s][d] layout, hi/lo bf16
#define AELEMS (BATCH * NH * SEQ * HD)
__device__ __nv_bfloat16 g_qh[AELEMS];
__device__ __nv_bfloat16 g_ql[AELEMS];
__device__ __nv_bfloat16 g_kh[AELEMS];
__device__ __nv_bfloat16 g_kl[AELEMS];
__device__ __nv_bfloat16 g_vh[AELEMS];
__device__ __nv_bfloat16 g_vl[AELEMS];

__device__ __forceinline__ uint32_t smem_to_u32(const void* p) {
    uint32_t a;
    asm("{ .reg .u64 t; cvta.to.shared.u64 t, %1; cvt.u32.u64 %0, t; }" : "=r"(a) : "l"(p));
    return a;
}
__device__ __forceinline__ void cp_async16(uint32_t dst, const void* src) {
    asm volatile("cp.async.cg.shared.global [%0], [%1], 16;" :: "r"(dst), "l"(src));
}
__device__ __forceinline__ void cp_commit() {
    asm volatile("cp.async.commit_group;" ::: "memory");
}
__device__ __forceinline__ void cp_wait1() {
    asm volatile("cp.async.wait_group 1;" ::: "memory");
}
__device__ __forceinline__ void ldsm_x4(uint32_t& r0, uint32_t& r1,
                                        uint32_t& r2, uint32_t& r3, uint32_t addr) {
    asm volatile("ldmatrix.sync.aligned.m8n8.x4.shared.b16 {%0,%1,%2,%3}, [%4];"
        : "=r"(r0), "=r"(r1), "=r"(r2), "=r"(r3) : "r"(addr));
}
__device__ __forceinline__ void ldsm_x4_t(uint32_t& r0, uint32_t& r1,
                                          uint32_t& r2, uint32_t& r3, uint32_t addr) {
    asm volatile("ldmatrix.sync.aligned.m8n8.x4.trans.shared.b16 {%0,%1,%2,%3}, [%4];"
        : "=r"(r0), "=r"(r1), "=r"(r2), "=r"(r3) : "r"(addr));
}
__device__ __forceinline__ void mma_bf16(float& c0, float& c1, float& c2, float& c3,
                                         uint32_t a0, uint32_t a1, uint32_t a2, uint32_t a3,
                                         uint32_t b0, uint32_t b1) {
    asm volatile(
        "mma.sync.aligned.m16n8k16.row.col.f32.bf16.bf16.f32 "
        "{%0,%1,%2,%3}, {%4,%5,%6,%7}, {%8,%9}, {%0,%1,%2,%3};"
        : "+f"(c0), "+f"(c1), "+f"(c2), "+f"(c3)
        : "r"(a0), "r"(a1), "r"(a2), "r"(a3), "r"(b0), "r"(b1));
}
__device__ __forceinline__ uint32_t pack_bf162(__nv_bfloat16 x, __nv_bfloat16 y) {
    __nv_bfloat162 t; t.x = x; t.y = y;
    return *reinterpret_cast<uint32_t*>(&t);
}
__device__ __forceinline__ void split2(float x, float y, uint32_t& hi, uint32_t& lo) {
    __nv_bfloat16 hx = __float2bfloat16(x), hy = __float2bfloat16(y);
    __nv_bfloat16 lx = __float2bfloat16(x - __bfloat162float(hx));
    __nv_bfloat16 ly = __float2bfloat16(y - __bfloat162float(hy));
    hi = pack_bf162(hx, hy);
    lo = pack_bf162(lx, ly);
}

// ---------------------------------------------------------------------------
// split: fp32 [R,K] -> bf16 [R,3K].  mode 0 (A): [hi|lo|hi]  mode 1 (B): [hi|hi|lo]
// ---------------------------------------------------------------------------
__global__ __launch_bounds__(256) void split_kernel(
    const float* __restrict__ in, __nv_bfloat16* __restrict__ out,
    int R, int K, int mode)
{
    int total = R * K;
    for (int i = blockIdx.x * blockDim.x + threadIdx.x; i < total;
         i += gridDim.x * blockDim.x) {
        int r = i / K, c = i % K;
        float a = in[i];
        __nv_bfloat16 hi = __float2bfloat16(a);
        __nv_bfloat16 lo = __float2bfloat16(a - __bfloat162float(hi));
        size_t base = (size_t)r * (3 * K) + c;
        out[base]         = hi;
        out[base + K]     = mode ? hi : lo;
        out[base + 2 * K] = mode ? lo : hi;
    }
}

// ---------------------------------------------------------------------------
// split qkv fp32 [b][s][6144] -> per-head hi/lo bf16 buffers [b*NH+h][s][128].
// Q gets pre-scaled by ATTN_SCALE before splitting.
// ---------------------------------------------------------------------------
__global__ __launch_bounds__(256) void split_qkv_kernel(const float* __restrict__ qkv)
{
    const int total = BATCH * SEQ * 3 * HID;
    for (int i = blockIdx.x * blockDim.x + threadIdx.x; i < total;
         i += gridDim.x * blockDim.x) {
        int bs = i / (3 * HID);           // b*SEQ + s
        int e  = i % (3 * HID);
        int seg = e >> 11;                // 0=Q 1=K 2=V
        int he  = e & 2047;
        int h   = he >> 7;
        int d   = he & 127;
        int b   = bs / SEQ, s = bs % SEQ;
        float f = qkv[i];
        if (seg == 0) f *= ATTN_SCALE;
        __nv_bfloat16 hi = __float2bfloat16(f);
        __nv_bfloat16 lo = __float2bfloat16(f - __bfloat162float(hi));
        size_t dst = ((size_t)(b * NH + h) * SEQ + s) * HD + d;
        if (seg == 0)      { g_qh[dst] = hi; g_ql[dst] = lo; }
        else if (seg == 1) { g_kh[dst] = hi; g_kl[dst] = lo; }
        else               { g_vh[dst] = hi; g_vl[dst] = lo; }
    }
}

// ---------------------------------------------------------------------------
// bf16 mma.sync GEMM (round-3, proven): C[M,N] = A[M,KP] * B[N,KP]^T
// ---------------------------------------------------------------------------
#define BM 128
#define BN 128
#define BK 64
#define STAGES 3
#define STAGE_BYTES (BM * 128 + BN * 128)
#define SM_TOTAL_G (STAGES * STAGE_BYTES)

__global__ void __launch_bounds__(256, 2) gemm_mma(
    int M, int N,
    const __nv_bfloat16* __restrict__ A,
    const __nv_bfloat16* __restrict__ B,
    float* __restrict__ C)
{
    extern __shared__ char smem[];
    const uint32_t smem_u = smem_to_u32(smem);
    const int tid  = threadIdx.x;
    const int wid  = tid >> 5;
    const int lane = tid & 31;
    const int wm = wid & 1;
    const int wn = wid >> 1;
    const int m0 = blockIdx.y * BM;
    const int n0 = blockIdx.x * BN;
    const int NT = KP / BK;

    auto load_stage = [&](int kt, int stage) {
        const uint32_t sA = smem_u + stage * STAGE_BYTES;
        const uint32_t sB = sA + BM * 128;
        const int k0 = kt * BK;
#pragma unroll
        for (int j = 0; j < 4; j++) {
            int i = tid + j * 256;
            int row = i >> 3;
            int c   = i & 7;
            uint32_t dsw = (uint32_t)(row * 128 + ((c ^ (row & 7)) << 4));
            cp_async16(sA + dsw, A + (size_t)(m0 + row) * KP + k0 + c * 8);
            cp_async16(sB + dsw, B + (size_t)(n0 + row) * KP + k0 + c * 8);
        }
        cp_commit();
    };

    float acc[4][4][4];
#pragma unroll
    for (int i = 0; i < 4; i++)
#pragma unroll
        for (int j = 0; j < 4; j++)
#pragma unroll
            for (int k = 0; k < 4; k++) acc[i][j][k] = 0.0f;

    load_stage(0, 0);
    load_stage(1, 1);

    const int a_row = wm * 64 + (lane & 15);
    const int a_chk = lane >> 4;
    const int b_row = wn * 32 + (lane & 7) + (((lane >> 4) & 1) << 3);
    const int b_chk = (lane >> 3) & 1;

    for (int kt = 0; kt < NT; kt++) {
        const int stage = kt % STAGES;
        cp_wait1();
        __syncthreads();
        if (kt + 2 < NT) load_stage(kt + 2, (kt + 2) % STAGES);

        const uint32_t sA = smem_u + stage * STAGE_BYTES;
        const uint32_t sB = sA + BM * 128;
#pragma unroll
        for (int ks = 0; ks < 4; ks++) {
            uint32_t a[4][4];
#pragma unroll
            for (int mi = 0; mi < 4; mi++) {
                int row = a_row + mi * 16;
                int chk = ks * 2 + a_chk;
                uint32_t addr = sA + (uint32_t)(row * 128 + ((chk ^ (row & 7)) << 4));
                ldsm_x4(a[mi][0], a[mi][1], a[mi][2], a[mi][3], addr);
            }
            uint32_t b[4][2];
#pragma unroll
            for (int p = 0; p < 2; p++) {
                int row = b_row + p * 16;
                int chk = ks * 2 + b_chk;
                uint32_t addr = sB + (uint32_t)(row * 128 + ((chk ^ (row & 7)) << 4));
                ldsm_x4(b[p * 2][0], b[p * 2][1], b[p * 2 + 1][0], b[p * 2 + 1][1], addr);
            }
#pragma unroll
            for (int mi = 0; mi < 4; mi++)
#pragma unroll
                for (int ni = 0; ni < 4; ni++)
                    mma_bf16(acc[mi][ni][0], acc[mi][ni][1], acc[mi][ni][2], acc[mi][ni][3],
                             a[mi][0], a[mi][1], a[mi][2], a[mi][3],
                             b[ni][0], b[ni][1]);
        }
        __syncthreads();
    }

    const int cr = lane >> 2;
    const int cc = (lane & 3) * 2;
#pragma unroll
    for (int mi = 0; mi < 4; mi++) {
        int row = m0 + wm * 64 + mi * 16 + cr;
#pragma unroll
        for (int ni = 0; ni < 4; ni++) {
            int col = n0 + wn * 32 + ni * 8 + cc;
            *reinterpret_cast<float2*>(C + (size_t)row * N + col) =
                make_float2(acc[mi][ni][0], acc[mi][ni][1]);
            *reinterpret_cast<float2*>(C + (size_t)(row + 8) * N + col) =
                make_float2(acc[mi][ni][2], acc[mi][ni][3]);
        }
    }
}

// ---------------------------------------------------------------------------
// Flash attention on mma.sync, bf16x3 in both GEMMs.
// BR=64 q-rows/CTA, BC=32 kv-rows/iter, 4 warps (16 rows each), 128 threads.
// SMEM: Qhi/Qlo [64][128]bf16 (rows 256B, 4-bit chunk swizzle) +
//       double-buffered {Khi,Klo,Vhi,Vlo}[32][128]bf16.  Total 96 KB.
// Writes output directly in split-A ([hi|lo|hi]) layout into g_as.
// ---------------------------------------------------------------------------
#define ABR 64
#define ABC 32
#define SMQ_HI 0
#define SMQ_LO 16384
#define SMKV   32768
#define KV_STRIDE 32768
#define AKH 0
#define AKL 8192
#define AVH 16384
#define AVL 24576
#define SM_TOTAL_A 98304

#define ASW(r, ch) ((uint32_t)((r) * 256 + ((((ch) ^ ((r) & 15))) << 4)))

__global__ void __launch_bounds__(128) attn_mma(
    __nv_bfloat16* __restrict__ out_as)
{
    extern __shared__ char smem[];
    const uint32_t smem_u = smem_to_u32(smem);
    const int tid  = threadIdx.x;
    const int w    = tid >> 5;
    const int lane = tid & 31;
    const int q0 = blockIdx.x * ABR;
    const int h  = blockIdx.y;
    const int b  = blockIdx.z;
    const size_t bh = (size_t)(b * NH + h) * SEQ;

    const __nv_bfloat16* qh = g_qh + (bh + q0) * HD;
    const __nv_bfloat16* ql = g_ql + (bh + q0) * HD;

    // ---- Q load (2 tensors x 64 rows x 16 chunks = 2048 chunks, 16/thread)
#pragma unroll
    for (int j = 0; j < 16; j++) {
        int i = tid + j * 128;
        int t   = i >> 10;            // 0=hi 1=lo
        int rem = i & 1023;
        int row = rem >> 4;
        int ch  = rem & 15;
        const __nv_bfloat16* src = (t == 0 ? qh : ql) + (size_t)row * HD + ch * 8;
        cp_async16(smem_u + (t == 0 ? SMQ_HI : SMQ_LO) + ASW(row, ch), src);
    }
    // ---- KV stage loader
    auto load_kv = [&](int kt, int stage) {
        const int j0 = kt * ABC;
        const uint32_t base = smem_u + SMKV + stage * KV_STRIDE;
#pragma unroll
        for (int j = 0; j < 16; j++) {
            int i = tid + j * 128;
            int t   = i >> 9;          // 0..3 : kh,kl,vh,vl
            int rem = i & 511;
            int row = rem >> 4;
            int ch  = rem & 15;
            const __nv_bfloat16* srcb =
                (t == 0 ? g_kh : t == 1 ? g_kl : t == 2 ? g_vh : g_vl);
            const __nv_bfloat16* src = srcb + (bh + j0 + row) * HD + ch * 8;
            cp_async16(base + t * 8192 + ASW(row, ch), src);
        }
        cp_commit();
    };

    load_kv(0, 0);   // group 0 (includes Q asyncs issued above)
    cp_commit();     // NOTE: Q+stage0 actually commit here as one group
    load_kv(1, 1);   // group 1

    float o[16][4];
#pragma unroll
    for (int nb = 0; nb < 16; nb++)
#pragma unroll
        for (int c = 0; c < 4; c++) o[nb][c] = 0.0f;
    float m_run[2] = {-1e30f, -1e30f};
    float l_run[2] = {0.0f, 0.0f};

    const int a_row = w * 16 + (lane & 15);
    const int a_chk = lane >> 4;
    const int b_rlo = (lane & 7) + (((lane >> 4) & 1) << 3);
    const int b_chk = (lane >> 3) & 1;
    const int v_row = (lane & 7) + (((lane >> 3) & 1) << 3);
    const int v_chk = lane >> 4;

    const int NT = SEQ / ABC;  // 64
    for (int kt = 0; kt < NT; kt++) {
        cp_wait1();
        __syncthreads();
        const uint32_t kvb = smem_u + SMKV + (kt & 1) * KV_STRIDE;

        // ---- S = Qhi*Khi + Qlo*Khi + Qhi*Klo  (16x32 per warp)
        float s[4][4];
#pragma unroll
        for (int nb = 0; nb < 4; nb++)
#pragma unroll
            for (int c = 0; c < 4; c++) s[nb][c] = 0.0f;

#pragma unroll
        for (int ks = 0; ks < 8; ks++) {
            uint32_t ah[4], al[4];
            {
                int chk = ks * 2 + a_chk;
                ldsm_x4(ah[0], ah[1], ah[2], ah[3], smem_u + SMQ_HI + ASW(a_row, chk));
                ldsm_x4(al[0], al[1], al[2], al[3], smem_u + SMQ_LO + ASW(a_row, chk));
            }
            uint32_t bh_[4][2], bl_[4][2];
#pragma unroll
            for (int p = 0; p < 2; p++) {
                int row = p * 16 + b_rlo;
                int chk = ks * 2 + b_chk;
                ldsm_x4(bh_[p*2][0], bh_[p*2][1], bh_[p*2+1][0], bh_[p*2+1][1],
                        kvb + AKH + ASW(row, chk));
                ldsm_x4(bl_[p*2][0], bl_[p*2][1], bl_[p*2+1][0], bl_[p*2+1][1],
                        kvb + AKL + ASW(row, chk));
            }
#pragma unroll
            for (int nb = 0; nb < 4; nb++) {
                mma_bf16(s[nb][0], s[nb][1], s[nb][2], s[nb][3],
                         ah[0], ah[1], ah[2], ah[3], bh_[nb][0], bh_[nb][1]);
                mma_bf16(s[nb][0], s[nb][1], s[nb][2], s[nb][3],
                         al[0], al[1], al[2], al[3], bh_[nb][0], bh_[nb][1]);
                mma_bf16(s[nb][0], s[nb][1], s[nb][2], s[nb][3],
                         ah[0], ah[1], ah[2], ah[3], bl_[nb][0], bl_[nb][1]);
            }
        }

        // ---- online softmax (rows g and g+8 per lane)
        float corr[2];
#pragma unroll
        for (int r2 = 0; r2 < 2; r2++) {
            float mloc = -1e30f;
#pragma unroll
            for (int nb = 0; nb < 4; nb++)
                mloc = fmaxf(mloc, fmaxf(s[nb][2*r2], s[nb][2*r2+1]));
            mloc = fmaxf(mloc, __shfl_xor_sync(0xffffffffu, mloc, 1));
            mloc = fmaxf(mloc, __shfl_xor_sync(0xffffffffu, mloc, 2));
            float m_new = fmaxf(m_run[r2], mloc);
            corr[r2] = __expf(m_run[r2] - m_new);
            m_run[r2] = m_new;
            float lloc = 0.0f;
#pragma unroll
            for (int nb = 0; nb < 4; nb++) {
                s[nb][2*r2]   = __expf(s[nb][2*r2]   - m_new);
                s[nb][2*r2+1] = __expf(s[nb][2*r2+1] - m_new);
                lloc += s[nb][2*r2] + s[nb][2*r2+1];
            }
            lloc += __shfl_xor_sync(0xffffffffu, lloc, 1);
            lloc += __shfl_xor_sync(0xffffffffu, lloc, 2);
            l_run[r2] = l_run[r2] * corr[r2] + lloc;
        }
#pragma unroll
        for (int nb = 0; nb < 16; nb++) {
            o[nb][0] *= corr[0]; o[nb][1] *= corr[0];
            o[nb][2] *= corr[1]; o[nb][3] *= corr[1];
        }

        // ---- O += Phi*Vhi + Plo*Vhi + Phi*Vlo
#pragma unroll
        for (int kc = 0; kc < 2; kc++) {
            uint32_t pah[4], pal[4];
            split2(s[2*kc][0],   s[2*kc][1],   pah[0], pal[0]);
            split2(s[2*kc][2],   s[2*kc][3],   pah[1], pal[1]);
            split2(s[2*kc+1][0], s[2*kc+1][1], pah[2], pal[2]);
            split2(s[2*kc+1][2], s[2*kc+1][3], pah[3], pal[3]);
            int row = kc * 16 + v_row;
#pragma unroll
            for (int nbp = 0; nbp < 8; nbp++) {
                int chk = nbp * 2 + v_chk;
                uint32_t vh0, vh1, vh2, vh3, vl0, vl1, vl2, vl3;
                ldsm_x4_t(vh0, vh1, vh2, vh3, kvb + AVH + ASW(row, chk));
                ldsm_x4_t(vl0, vl1, vl2, vl3, kvb + AVL + ASW(row, chk));
                int n0 = nbp * 2, n1 = nbp * 2 + 1;
                mma_bf16(o[n0][0], o[n0][1], o[n0][2], o[n0][3],
                         pah[0], pah[1], pah[2], pah[3], vh0, vh1);
                mma_bf16(o[n0][0], o[n0][1], o[n0][2], o[n0][3],
                         pal[0], pal[1], pal[2], pal[3], vh0, vh1);
                mma_bf16(o[n0][0], o[n0][1], o[n0][2], o[n0][3],
                         pah[0], pah[1], pah[2], pah[3], vl0, vl1);
                mma_bf16(o[n1][0], o[n1][1], o[n1][2], o[n1][3],
                         pah[0], pah[1], pah[2], pah[3], vh2, vh3);
                mma_bf16(o[n1][0], o[n1][1], o[n1][2], o[n1][3],
                         pal[0], pal[1], pal[2], pal[3], vh2, vh3);
                mma_bf16(o[n1][0], o[n1][1], o[n1][2], o[n1][3],
                         pah[0], pah[1], pah[2], pah[3], vl2, vl3);
            }
        }

        __syncthreads();
        if (kt + 2 < NT) load_kv(kt + 2, kt & 1);
    }

    // ---- write output in split-A layout: [hi | lo | hi] at row s, col h*128+..
    const int g  = lane >> 2;
    const int t2 = (lane & 3) * 2;
    float inv0 = 1.0f / l_run[0];
    float inv1 = 1.0f / l_run[1];
#pragma unroll
    for (int r2 = 0; r2 < 2; r2++) {
        int srow = q0 + w * 16 + g + r2 * 8;
        float inv = r2 ? inv1 : inv0;
        size_t rbase = ((size_t)(b * SEQ + srow)) * KP + h * HD + t2;
#pragma unroll
        for (int nb = 0; nb < 16; nb++) {
            float v0 = o[nb][2*r2]   * inv;
            float v1 = o[nb][2*r2+1] * inv;
            uint32_t hi, lo;
            split2(v0, v1, hi, lo);
            size_t cbase = rbase + nb * 8;
            *reinterpret_cast<uint32_t*>(out_as + cbase)            = hi;
            *reinterpret_cast<uint32_t*>(out_as + cbase + HID)      = lo;
            *reinterpret_cast<uint32_t*>(out_as + cbase + 2 * HID)  = hi;
        }
    }
}

// ---------------------------------------------------------------------------
extern "C" void kernel_launch(void* const* d_in, const int* in_sizes, int n_in,
                              void* d_out, int out_size)
{
    const float* x      = (const float*)d_in[0];
    const float* w_qkv  = (const float*)d_in[1];
    const float* w_proj = (const float*)d_in[2];
    float* out = (float*)d_out;

    float* qkv_ptr = nullptr;
    __nv_bfloat16 *as_ptr = nullptr, *ws1_ptr = nullptr, *ws2_ptr = nullptr;
    cudaGetSymbolAddress((void**)&qkv_ptr, g_qkv);
    cudaGetSymbolAddress((void**)&as_ptr,  g_as);
    cudaGetSymbolAddress((void**)&ws1_ptr, g_ws1);
    cudaGetSymbolAddress((void**)&ws2_ptr, g_ws2);

    cudaFuncSetAttribute(gemm_mma,
                         cudaFuncAttributeMaxDynamicSharedMemorySize, SM_TOTAL_G);
    cudaFuncSetAttribute(attn_mma,
                         cudaFuncAttributeMaxDynamicSharedMemorySize, SM_TOTAL_A);

    const int M = BATCH * SEQ;  // 4096

    // splits (bf16x3 via K-concat)
    split_kernel<<<4096, 256>>>(x,      as_ptr,  M,       HID, 0);
    split_kernel<<<4096, 256>>>(w_qkv,  ws1_ptr, 3 * HID, HID, 1);
    split_kernel<<<2048, 256>>>(w_proj, ws2_ptr, HID,     HID, 1);

    // 1) qkv = x @ w_qkv^T : [4096, 6144]
    gemm_mma<<<dim3(3 * HID / BN, M / BM), 256, SM_TOTAL_G>>>(
        M, 3 * HID, as_ptr, ws1_ptr, qkv_ptr);

    // 2) split qkv into per-head hi/lo bf16 (Q pre-scaled)
    split_qkv_kernel<<<8192, 256>>>(qkv_ptr);

    // 3) flash attention (writes split-A layout into g_as)
    attn_mma<<<dim3(SEQ / ABR, NH, BATCH), 128, SM_TOTAL_A>>>(as_ptr);

    // 4) out = attn @ w_proj^T : [4096, 2048]
    gemm_mma<<<dim3(HID / BN, M / BM), 256, SM_TOTAL_G>>>(
        M, HID, as_ptr, ws2_ptr, out);
}

// round 5
// speedup vs baseline: 4.0169x; 1.0285x over previous
#include <cuda_runtime.h>
#include <cuda_bf16.h>
#include <cstdint>

#define SEQ  2048
#define HID  2048
#define NH   16
#define HD   128
#define BATCH 2
#define ATTN_SCALE 0.08838834764831845f
#define KP   6144   // B-operand split K' = 3*2048
#define KA   4096   // A-operand split K  = 2*2048  ([hi|lo], third block remapped)

// ---------------- scratch (no allocs allowed) ----------------
__device__ __nv_bfloat16 g_as[BATCH * SEQ * KA];   // split A operand (x, later attn out)
__device__ __nv_bfloat16 g_ws1[3 * HID * KP];      // split w_qkv  [hi|hi|lo]
__device__ __nv_bfloat16 g_ws2[HID * KP];          // split w_proj [hi|hi|lo]
// attention operands, [b*NH+h][s][d] layout, hi/lo bf16
#define AELEMS (BATCH * NH * SEQ * HD)
__device__ __nv_bfloat16 g_qh[AELEMS];
__device__ __nv_bfloat16 g_ql[AELEMS];
__device__ __nv_bfloat16 g_kh[AELEMS];
__device__ __nv_bfloat16 g_kl[AELEMS];
__device__ __nv_bfloat16 g_vh[AELEMS];
__device__ __nv_bfloat16 g_vl[AELEMS];

__device__ __forceinline__ uint32_t smem_to_u32(const void* p) {
    uint32_t a;
    asm("{ .reg .u64 t; cvta.to.shared.u64 t, %1; cvt.u32.u64 %0, t; }" : "=r"(a) : "l"(p));
    return a;
}
__device__ __forceinline__ void cp_async16(uint32_t dst, const void* src) {
    asm volatile("cp.async.cg.shared.global [%0], [%1], 16;" :: "r"(dst), "l"(src));
}
__device__ __forceinline__ void cp_commit() {
    asm volatile("cp.async.commit_group;" ::: "memory");
}
__device__ __forceinline__ void cp_wait1() {
    asm volatile("cp.async.wait_group 1;" ::: "memory");
}
__device__ __forceinline__ void ldsm_x4(uint32_t& r0, uint32_t& r1,
                                        uint32_t& r2, uint32_t& r3, uint32_t addr) {
    asm volatile("ldmatrix.sync.aligned.m8n8.x4.shared.b16 {%0,%1,%2,%3}, [%4];"
        : "=r"(r0), "=r"(r1), "=r"(r2), "=r"(r3) : "r"(addr));
}
__device__ __forceinline__ void ldsm_x4_t(uint32_t& r0, uint32_t& r1,
                                          uint32_t& r2, uint32_t& r3, uint32_t addr) {
    asm volatile("ldmatrix.sync.aligned.m8n8.x4.trans.shared.b16 {%0,%1,%2,%3}, [%4];"
        : "=r"(r0), "=r"(r1), "=r"(r2), "=r"(r3) : "r"(addr));
}
__device__ __forceinline__ void mma_bf16(float& c0, float& c1, float& c2, float& c3,
                                         uint32_t a0, uint32_t a1, uint32_t a2, uint32_t a3,
                                         uint32_t b0, uint32_t b1) {
    asm volatile(
        "mma.sync.aligned.m16n8k16.row.col.f32.bf16.bf16.f32 "
        "{%0,%1,%2,%3}, {%4,%5,%6,%7}, {%8,%9}, {%0,%1,%2,%3};"
        : "+f"(c0), "+f"(c1), "+f"(c2), "+f"(c3)
        : "r"(a0), "r"(a1), "r"(a2), "r"(a3), "r"(b0), "r"(b1));
}
__device__ __forceinline__ uint32_t pack_bf162(__nv_bfloat16 x, __nv_bfloat16 y) {
    __nv_bfloat162 t; t.x = x; t.y = y;
    return *reinterpret_cast<uint32_t*>(&t);
}
__device__ __forceinline__ void split2(float x, float y, uint32_t& hi, uint32_t& lo) {
    __nv_bfloat16 hx = __float2bfloat16(x), hy = __float2bfloat16(y);
    __nv_bfloat16 lx = __float2bfloat16(x - __bfloat162float(hx));
    __nv_bfloat16 ly = __float2bfloat16(y - __bfloat162float(hy));
    hi = pack_bf162(hx, hy);
    lo = pack_bf162(lx, ly);
}

// ---------------------------------------------------------------------------
// split: fp32 [R,K] -> bf16.  mode 0 (A): [hi|lo]   (row stride 2K)
//                             mode 1 (B): [hi|hi|lo] (row stride 3K)
// ---------------------------------------------------------------------------
__global__ __launch_bounds__(256) void split_kernel(
    const float* __restrict__ in, __nv_bfloat16* __restrict__ out,
    int R, int K, int mode)
{
    int total = R * K;
    for (int i = blockIdx.x * blockDim.x + threadIdx.x; i < total;
         i += gridDim.x * blockDim.x) {
        int r = i / K, c = i % K;
        float a = in[i];
        __nv_bfloat16 hi = __float2bfloat16(a);
        __nv_bfloat16 lo = __float2bfloat16(a - __bfloat162float(hi));
        if (mode == 0) {
            size_t base = (size_t)r * (2 * K) + c;
            out[base]     = hi;
            out[base + K] = lo;
        } else {
            size_t base = (size_t)r * (3 * K) + c;
            out[base]         = hi;
            out[base + K]     = hi;
            out[base + 2 * K] = lo;
        }
    }
}

// ---------------------------------------------------------------------------
// Shared GEMM mainloop pieces. A is [M,KA]=[hi|lo] with kt remap (effective
// K' = [hi|lo|hi]); B is [N,KP]=[hi|hi|lo]. CTA tile 128x128, BK=64, 3 stages.
// ---------------------------------------------------------------------------
#define BM 128
#define BN 128
#define BK 64
#define STAGES 3
#define STAGE_BYTES (BM * 128 + BN * 128)
#define SM_TOTAL_G (STAGES * STAGE_BYTES)
#define NT_G (KP / BK)   // 96

#define GEMM_MAINLOOP(A_, B_, accvar)                                              \
    extern __shared__ char smem[];                                                 \
    const uint32_t smem_u = smem_to_u32(smem);                                     \
    const int tid  = threadIdx.x;                                                  \
    const int wid  = tid >> 5;                                                     \
    const int lane = tid & 31;                                                     \
    const int wm = wid & 1;                                                        \
    const int wn = wid >> 1;                                                       \
    const int m0 = blockIdx.y * BM;                                                \
    const int n0 = blockIdx.x * BN;                                                \
    auto load_stage = [&](int kt, int stage) {                                     \
        const uint32_t sA = smem_u + stage * STAGE_BYTES;                          \
        const uint32_t sB = sA + BM * 128;                                         \
        const int akt = (kt < 64) ? kt : kt - 64;                                  \
        const int ka0 = akt * BK;                                                  \
        const int kb0 = kt * BK;                                                   \
        _Pragma("unroll")                                                          \
        for (int j = 0; j < 4; j++) {                                              \
            int i = tid + j * 256;                                                 \
            int row = i >> 3;                                                      \
            int c   = i & 7;                                                       \
            uint32_t dsw = (uint32_t)(row * 128 + ((c ^ (row & 7)) << 4));         \
            cp_async16(sA + dsw, A_ + (size_t)(m0 + row) * KA + ka0 + c * 8);      \
            cp_async16(sB + dsw, B_ + (size_t)(n0 + row) * KP + kb0 + c * 8);      \
        }                                                                          \
        cp_commit();                                                               \
    };                                                                             \
    float accvar[4][4][4];                                                         \
    _Pragma("unroll")                                                              \
    for (int i = 0; i < 4; i++)                                                    \
        _Pragma("unroll")                                                          \
        for (int j = 0; j < 4; j++)                                                \
            _Pragma("unroll")                                                      \
            for (int k = 0; k < 4; k++) accvar[i][j][k] = 0.0f;                    \
    load_stage(0, 0);                                                              \
    load_stage(1, 1);                                                              \
    const int a_row = wm * 64 + (lane & 15);                                       \
    const int a_chk = lane >> 4;                                                   \
    const int b_row = wn * 32 + (lane & 7) + (((lane >> 4) & 1) << 3);             \
    const int b_chk = (lane >> 3) & 1;                                             \
    for (int kt = 0; kt < NT_G; kt++) {                                            \
        const int stage = kt % STAGES;                                             \
        cp_wait1();                                                                \
        __syncthreads();                                                           \
        if (kt + 2 < NT_G) load_stage(kt + 2, (kt + 2) % STAGES);                  \
        const uint32_t sA = smem_u + stage * STAGE_BYTES;                          \
        const uint32_t sB = sA + BM * 128;                                         \
        _Pragma("unroll")                                                          \
        for (int ks = 0; ks < 4; ks++) {                                           \
            uint32_t a[4][4];                                                      \
            _Pragma("unroll")                                                      \
            for (int mi = 0; mi < 4; mi++) {                                       \
                int row = a_row + mi * 16;                                         \
                int chk = ks * 2 + a_chk;                                          \
                uint32_t addr = sA + (uint32_t)(row * 128 + ((chk ^ (row & 7)) << 4)); \
                ldsm_x4(a[mi][0], a[mi][1], a[mi][2], a[mi][3], addr);             \
            }                                                                      \
            uint32_t bfr[4][2];                                                    \
            _Pragma("unroll")                                                      \
            for (int p = 0; p < 2; p++) {                                          \
                int row = b_row + p * 16;                                          \
                int chk = ks * 2 + b_chk;                                          \
                uint32_t addr = sB + (uint32_t)(row * 128 + ((chk ^ (row & 7)) << 4)); \
                ldsm_x4(bfr[p * 2][0], bfr[p * 2][1], bfr[p * 2 + 1][0], bfr[p * 2 + 1][1], addr); \
            }                                                                      \
            _Pragma("unroll")                                                      \
            for (int mi = 0; mi < 4; mi++)                                         \
                _Pragma("unroll")                                                  \
                for (int ni = 0; ni < 4; ni++)                                     \
                    mma_bf16(accvar[mi][ni][0], accvar[mi][ni][1],                 \
                             accvar[mi][ni][2], accvar[mi][ni][3],                 \
                             a[mi][0], a[mi][1], a[mi][2], a[mi][3],               \
                             bfr[ni][0], bfr[ni][1]);                              \
        }                                                                          \
        __syncthreads();                                                           \
    }

// GEMM1: qkv = x @ w_qkv^T, epilogue writes split per-head Q/K/V hi/lo directly.
__global__ void __launch_bounds__(256, 2) gemm_qkv(
    const __nv_bfloat16* __restrict__ A,
    const __nv_bfloat16* __restrict__ B)
{
    GEMM_MAINLOOP(A, B, acc)

    // epilogue: this N-tile is exactly one (seg, head): 6144 = 3*16*128
    const int seg = n0 >> 11;                 // 0=Q 1=K 2=V
    const int h   = (n0 & 2047) >> 7;
    __nv_bfloat16 *dh, *dl;
    float scale;
    if (seg == 0)      { dh = g_qh; dl = g_ql; scale = ATTN_SCALE; }
    else if (seg == 1) { dh = g_kh; dl = g_kl; scale = 1.0f; }
    else               { dh = g_vh; dl = g_vl; scale = 1.0f; }

    const int cr = lane >> 2;
    const int cc = (lane & 3) * 2;
#pragma unroll
    for (int mi = 0; mi < 4; mi++) {
        int row = m0 + wm * 64 + mi * 16 + cr;     // b*SEQ + s
#pragma unroll
        for (int ni = 0; ni < 4; ni++) {
            int d = wn * 32 + ni * 8 + cc;
#pragma unroll
            for (int r2 = 0; r2 < 2; r2++) {
                int rr = row + r2 * 8;
                int b = rr >> 11, s = rr & 2047;
                size_t dst = ((size_t)(b * NH + h) * SEQ + s) * HD + d;
                uint32_t hi, lo;
                split2(acc[mi][ni][2 * r2] * scale, acc[mi][ni][2 * r2 + 1] * scale, hi, lo);
                *reinterpret_cast<uint32_t*>(dh + dst) = hi;
                *reinterpret_cast<uint32_t*>(dl + dst) = lo;
            }
        }
    }
}

// GEMM2: out = attn @ w_proj^T, fp32 epilogue.
__global__ void __launch_bounds__(256, 2) gemm_out(
    int N,
    const __nv_bfloat16* __restrict__ A,
    const __nv_bfloat16* __restrict__ B,
    float* __restrict__ C)
{
    GEMM_MAINLOOP(A, B, acc)

    const int cr = lane >> 2;
    const int cc = (lane & 3) * 2;
#pragma unroll
    for (int mi = 0; mi < 4; mi++) {
        int row = m0 + wm * 64 + mi * 16 + cr;
#pragma unroll
        for (int ni = 0; ni < 4; ni++) {
            int col = n0 + wn * 32 + ni * 8 + cc;
            *reinterpret_cast<float2*>(C + (size_t)row * N + col) =
                make_float2(acc[mi][ni][0], acc[mi][ni][1]);
            *reinterpret_cast<float2*>(C + (size_t)(row + 8) * N + col) =
                make_float2(acc[mi][ni][2], acc[mi][ni][3]);
        }
    }
}

// ---------------------------------------------------------------------------
// Flash attention on mma.sync (round-4, proven), output now [hi|lo] (stride KA)
// ---------------------------------------------------------------------------
#define ABR 64
#define ABC 32
#define SMQ_HI 0
#define SMQ_LO 16384
#define SMKV   32768
#define KV_STRIDE 32768
#define AKH 0
#define AKL 8192
#define AVH 16384
#define AVL 24576
#define SM_TOTAL_A 98304

#define ASW(r, ch) ((uint32_t)((r) * 256 + ((((ch) ^ ((r) & 15))) << 4)))

__global__ void __launch_bounds__(128) attn_mma(
    __nv_bfloat16* __restrict__ out_as)
{
    extern __shared__ char smem[];
    const uint32_t smem_u = smem_to_u32(smem);
    const int tid  = threadIdx.x;
    const int w    = tid >> 5;
    const int lane = tid & 31;
    const int q0 = blockIdx.x * ABR;
    const int h  = blockIdx.y;
    const int b  = blockIdx.z;
    const size_t bh = (size_t)(b * NH + h) * SEQ;

    const __nv_bfloat16* qh = g_qh + (bh + q0) * HD;
    const __nv_bfloat16* ql = g_ql + (bh + q0) * HD;

#pragma unroll
    for (int j = 0; j < 16; j++) {
        int i = tid + j * 128;
        int t   = i >> 10;
        int rem = i & 1023;
        int row = rem >> 4;
        int ch  = rem & 15;
        const __nv_bfloat16* src = (t == 0 ? qh : ql) + (size_t)row * HD + ch * 8;
        cp_async16(smem_u + (t == 0 ? SMQ_HI : SMQ_LO) + ASW(row, ch), src);
    }
    auto load_kv = [&](int kt, int stage) {
        const int j0 = kt * ABC;
        const uint32_t base = smem_u + SMKV + stage * KV_STRIDE;
#pragma unroll
        for (int j = 0; j < 16; j++) {
            int i = tid + j * 128;
            int t   = i >> 9;
            int rem = i & 511;
            int row = rem >> 4;
            int ch  = rem & 15;
            const __nv_bfloat16* srcb =
                (t == 0 ? g_kh : t == 1 ? g_kl : t == 2 ? g_vh : g_vl);
            const __nv_bfloat16* src = srcb + (bh + j0 + row) * HD + ch * 8;
            cp_async16(base + t * 8192 + ASW(row, ch), src);
        }
        cp_commit();
    };

    load_kv(0, 0);
    cp_commit();
    load_kv(1, 1);

    float o[16][4];
#pragma unroll
    for (int nb = 0; nb < 16; nb++)
#pragma unroll
        for (int c = 0; c < 4; c++) o[nb][c] = 0.0f;
    float m_run[2] = {-1e30f, -1e30f};
    float l_run[2] = {0.0f, 0.0f};

    const int a_row = w * 16 + (lane & 15);
    const int a_chk = lane >> 4;
    const int b_rlo = (lane & 7) + (((lane >> 4) & 1) << 3);
    const int b_chk = (lane >> 3) & 1;
    const int v_row = (lane & 7) + (((lane >> 3) & 1) << 3);
    const int v_chk = lane >> 4;

    const int NT = SEQ / ABC;
    for (int kt = 0; kt < NT; kt++) {
        cp_wait1();
        __syncthreads();
        const uint32_t kvb = smem_u + SMKV + (kt & 1) * KV_STRIDE;

        float s[4][4];
#pragma unroll
        for (int nb = 0; nb < 4; nb++)
#pragma unroll
            for (int c = 0; c < 4; c++) s[nb][c] = 0.0f;

#pragma unroll
        for (int ks = 0; ks < 8; ks++) {
            uint32_t ah[4], al[4];
            {
                int chk = ks * 2 + a_chk;
                ldsm_x4(ah[0], ah[1], ah[2], ah[3], smem_u + SMQ_HI + ASW(a_row, chk));
                ldsm_x4(al[0], al[1], al[2], al[3], smem_u + SMQ_LO + ASW(a_row, chk));
            }
            uint32_t bh_[4][2], bl_[4][2];
#pragma unroll
            for (int p = 0; p < 2; p++) {
                int row = p * 16 + b_rlo;
                int chk = ks * 2 + b_chk;
                ldsm_x4(bh_[p*2][0], bh_[p*2][1], bh_[p*2+1][0], bh_[p*2+1][1],
                        kvb + AKH + ASW(row, chk));
                ldsm_x4(bl_[p*2][0], bl_[p*2][1], bl_[p*2+1][0], bl_[p*2+1][1],
                        kvb + AKL + ASW(row, chk));
            }
#pragma unroll
            for (int nb = 0; nb < 4; nb++) {
                mma_bf16(s[nb][0], s[nb][1], s[nb][2], s[nb][3],
                         ah[0], ah[1], ah[2], ah[3], bh_[nb][0], bh_[nb][1]);
                mma_bf16(s[nb][0], s[nb][1], s[nb][2], s[nb][3],
                         al[0], al[1], al[2], al[3], bh_[nb][0], bh_[nb][1]);
                mma_bf16(s[nb][0], s[nb][1], s[nb][2], s[nb][3],
                         ah[0], ah[1], ah[2], ah[3], bl_[nb][0], bl_[nb][1]);
            }
        }

        float corr[2];
#pragma unroll
        for (int r2 = 0; r2 < 2; r2++) {
            float mloc = -1e30f;
#pragma unroll
            for (int nb = 0; nb < 4; nb++)
                mloc = fmaxf(mloc, fmaxf(s[nb][2*r2], s[nb][2*r2+1]));
            mloc = fmaxf(mloc, __shfl_xor_sync(0xffffffffu, mloc, 1));
            mloc = fmaxf(mloc, __shfl_xor_sync(0xffffffffu, mloc, 2));
            float m_new = fmaxf(m_run[r2], mloc);
            corr[r2] = __expf(m_run[r2] - m_new);
            m_run[r2] = m_new;
            float lloc = 0.0f;
#pragma unroll
            for (int nb = 0; nb < 4; nb++) {
                s[nb][2*r2]   = __expf(s[nb][2*r2]   - m_new);
                s[nb][2*r2+1] = __expf(s[nb][2*r2+1] - m_new);
                lloc += s[nb][2*r2] + s[nb][2*r2+1];
            }
            lloc += __shfl_xor_sync(0xffffffffu, lloc, 1);
            lloc += __shfl_xor_sync(0xffffffffu, lloc, 2);
            l_run[r2] = l_run[r2] * corr[r2] + lloc;
        }
#pragma unroll
        for (int nb = 0; nb < 16; nb++) {
            o[nb][0] *= corr[0]; o[nb][1] *= corr[0];
            o[nb][2] *= corr[1]; o[nb][3] *= corr[1];
        }

#pragma unroll
        for (int kc = 0; kc < 2; kc++) {
            uint32_t pah[4], pal[4];
            split2(s[2*kc][0],   s[2*kc][1],   pah[0], pal[0]);
            split2(s[2*kc][2],   s[2*kc][3],   pah[1], pal[1]);
            split2(s[2*kc+1][0], s[2*kc+1][1], pah[2], pal[2]);
            split2(s[2*kc+1][2], s[2*kc+1][3], pah[3], pal[3]);
            int row = kc * 16 + v_row;
#pragma unroll
            for (int nbp = 0; nbp < 8; nbp++) {
                int chk = nbp * 2 + v_chk;
                uint32_t vh0, vh1, vh2, vh3, vl0, vl1, vl2, vl3;
                ldsm_x4_t(vh0, vh1, vh2, vh3, kvb + AVH + ASW(row, chk));
                ldsm_x4_t(vl0, vl1, vl2, vl3, kvb + AVL + ASW(row, chk));
                int n0 = nbp * 2, n1 = nbp * 2 + 1;
                mma_bf16(o[n0][0], o[n0][1], o[n0][2], o[n0][3],
                         pah[0], pah[1], pah[2], pah[3], vh0, vh1);
                mma_bf16(o[n0][0], o[n0][1], o[n0][2], o[n0][3],
                         pal[0], pal[1], pal[2], pal[3], vh0, vh1);
                mma_bf16(o[n0][0], o[n0][1], o[n0][2], o[n0][3],
                         pah[0], pah[1], pah[2], pah[3], vl0, vl1);
                mma_bf16(o[n1][0], o[n1][1], o[n1][2], o[n1][3],
                         pah[0], pah[1], pah[2], pah[3], vh2, vh3);
                mma_bf16(o[n1][0], o[n1][1], o[n1][2], o[n1][3],
                         pal[0], pal[1], pal[2], pal[3], vh2, vh3);
                mma_bf16(o[n1][0], o[n1][1], o[n1][2], o[n1][3],
                         pah[0], pah[1], pah[2], pah[3], vl2, vl3);
            }
        }

        __syncthreads();
        if (kt + 2 < NT) load_kv(kt + 2, kt & 1);
    }

    // write output in split-A 2-block layout: hi at +0, lo at +HID (row stride KA)
    const int g  = lane >> 2;
    const int t2 = (lane & 3) * 2;
    float inv0 = 1.0f / l_run[0];
    float inv1 = 1.0f / l_run[1];
#pragma unroll
    for (int r2 = 0; r2 < 2; r2++) {
        int srow = q0 + w * 16 + g + r2 * 8;
        float inv = r2 ? inv1 : inv0;
        size_t rbase = ((size_t)(b * SEQ + srow)) * KA + h * HD + t2;
#pragma unroll
        for (int nb = 0; nb < 16; nb++) {
            float v0 = o[nb][2*r2]   * inv;
            float v1 = o[nb][2*r2+1] * inv;
            uint32_t hi, lo;
            split2(v0, v1, hi, lo);
            size_t cbase = rbase + nb * 8;
            *reinterpret_cast<uint32_t*>(out_as + cbase)       = hi;
            *reinterpret_cast<uint32_t*>(out_as + cbase + HID) = lo;
        }
    }
}

// ---------------------------------------------------------------------------
extern "C" void kernel_launch(void* const* d_in, const int* in_sizes, int n_in,
                              void* d_out, int out_size)
{
    const float* x      = (const float*)d_in[0];
    const float* w_qkv  = (const float*)d_in[1];
    const float* w_proj = (const float*)d_in[2];
    float* out = (float*)d_out;

    __nv_bfloat16 *as_ptr = nullptr, *ws1_ptr = nullptr, *ws2_ptr = nullptr;
    cudaGetSymbolAddress((void**)&as_ptr,  g_as);
    cudaGetSymbolAddress((void**)&ws1_ptr, g_ws1);
    cudaGetSymbolAddress((void**)&ws2_ptr, g_ws2);

    cudaFuncSetAttribute(gemm_qkv,
                         cudaFuncAttributeMaxDynamicSharedMemorySize, SM_TOTAL_G);
    cudaFuncSetAttribute(gemm_out,
                         cudaFuncAttributeMaxDynamicSharedMemorySize, SM_TOTAL_G);
    cudaFuncSetAttribute(attn_mma,
                         cudaFuncAttributeMaxDynamicSharedMemorySize, SM_TOTAL_A);

    const int M = BATCH * SEQ;  // 4096

    // splits: A-form [hi|lo], B-form [hi|hi|lo]
    split_kernel<<<4096, 256>>>(x,      as_ptr,  M,       HID, 0);
    split_kernel<<<4096, 256>>>(w_qkv,  ws1_ptr, 3 * HID, HID, 1);
    split_kernel<<<2048, 256>>>(w_proj, ws2_ptr, HID,     HID, 1);

    // 1) fused: qkv GEMM + per-head hi/lo split epilogue (Q pre-scaled)
    gemm_qkv<<<dim3(3 * HID / BN, M / BM), 256, SM_TOTAL_G>>>(as_ptr, ws1_ptr);

    // 2) flash attention (writes split-A layout into g_as)
    attn_mma<<<dim3(SEQ / ABR, NH, BATCH), 128, SM_TOTAL_A>>>(as_ptr);

    // 3) out = attn @ w_proj^T
    gemm_out<<<dim3(HID / BN, M / BM), 256, SM_TOTAL_G>>>(HID, as_ptr, ws2_ptr, out);
}